// round 10
// baseline (speedup 1.0000x reference)
#include <cuda_runtime.h>
#include <cstdint>

// ---------------------------------------------------------------------------
// MaskMultiheadAttention  (B=4, N=2048, C=256, H=8, Dh=32)
// out = (query + proj_o(attn_masked @ V), softmax(QK^T*scale))
// d_out layout: [out_query (B*N*C floats)] [attn_vis (B*H*N*N floats)]
// Attention inner GEMMs on tensor cores via mma.sync tf32 (base sm_103 ISA).
// ---------------------------------------------------------------------------

constexpr int B_ = 4, N_ = 2048, C_ = 256, H_ = 8, D_ = 32;
constexpr float SCALE_L2 = 0.17677669529663687f * 1.4426950408889634f;

__device__ float g_q [B_ * N_ * C_];
__device__ float g_k [B_ * N_ * C_];
__device__ float g_kt[B_ * H_ * D_ * N_];   // K^T: [b][h][d][token]
__device__ float g_v [B_ * N_ * C_];
__device__ float g_x [B_ * N_ * C_];
__device__ int   g_cmax[B_ * N_];

#define DEV_INLINE __device__ __forceinline__
typedef unsigned long long ull;

DEV_INLINE ull pk2(float lo, float hi) {
    ull r; asm("mov.b64 %0, {%1, %2};" : "=l"(r) : "f"(lo), "f"(hi)); return r;
}
DEV_INLINE float2 upk2(ull v) {
    float2 f; asm("mov.b64 {%0, %1}, %2;" : "=f"(f.x), "=f"(f.y) : "l"(v)); return f;
}
DEV_INLINE ull ffma2(ull a, ull b, ull c) {
    ull d; asm("fma.rn.f32x2 %0, %1, %2, %3;" : "=l"(d) : "l"(a), "l"(b), "l"(c)); return d;
}
DEV_INLINE float ex2f(float x) {
    float y; asm("ex2.approx.ftz.f32 %0, %1;" : "=f"(y) : "f"(x)); return y;
}
DEV_INLINE float tf32r(float x) {            // round-to-nearest tf32, as f32 bits
    uint32_t r; asm("cvt.rna.tf32.f32 %0, %1;" : "=r"(r) : "f"(x));
    return __uint_as_float(r);
}
DEV_INLINE uint32_t fb(float x) { return __float_as_uint(x); }

// m16n8k8 tf32 MMA, row.col. Documented per-lane layout (g=lane>>2, tq=lane&3):
//  A: a0=(g,tq) a1=(g+8,tq) a2=(g,tq+4) a3=(g+8,tq+4)
//  B: b0=(k=tq,n=g) b1=(k=tq+4,n=g)
//  D: d0=(g,2tq) d1=(g,2tq+1) d2=(g+8,2tq) d3=(g+8,2tq+1)
DEV_INLINE void mma8(float4& d, uint32_t a0, uint32_t a1, uint32_t a2, uint32_t a3,
                     uint32_t b0, uint32_t b1) {
    asm volatile("mma.sync.aligned.m16n8k8.row.col.f32.tf32.tf32.f32 "
                 "{%0,%1,%2,%3}, {%4,%5,%6,%7}, {%8,%9}, {%0,%1,%2,%3};"
                 : "+f"(d.x), "+f"(d.y), "+f"(d.z), "+f"(d.w)
                 : "r"(a0), "r"(a1), "r"(a2), "r"(a3), "r"(b0), "r"(b1));
}

// ---------------------------------------------------------------------------
// QKV GEMM (NT, fused 3 outputs) — FFMA2 (proven)
// ---------------------------------------------------------------------------
__global__ void __launch_bounds__(256) gemm_qkv(
    const float* __restrict__ A,
    const float* __restrict__ W0, const float* __restrict__ b0, float* __restrict__ o0,
    const float* __restrict__ W1, const float* __restrict__ b1, float* __restrict__ o1,
    const float* __restrict__ W2, const float* __restrict__ b2, float* __restrict__ o2) {
    __shared__ float As[2][16][64];
    __shared__ float Bs[2][3][16][64];
    const int t  = threadIdx.x;
    const int m0 = blockIdx.y * 64;
    const int n0 = blockIdx.x * 64;
    const int ty = t >> 4, tx = t & 15;
    const int lr = t >> 2;
    const int lk = (t & 3) * 4;

    const float4* Ap  = (const float4*)&A [(size_t)(m0 + lr) * C_ + lk];
    const float4* W0p = (const float4*)&W0[(size_t)(n0 + lr) * C_ + lk];
    const float4* W1p = (const float4*)&W1[(size_t)(n0 + lr) * C_ + lk];
    const float4* W2p = (const float4*)&W2[(size_t)(n0 + lr) * C_ + lk];

    float4 sa = Ap[0], s0 = W0p[0], s1 = W1p[0], s2 = W2p[0];
    {
        As[0][lk+0][lr]=sa.x; As[0][lk+1][lr]=sa.y; As[0][lk+2][lr]=sa.z; As[0][lk+3][lr]=sa.w;
        Bs[0][0][lk+0][lr]=s0.x; Bs[0][0][lk+1][lr]=s0.y; Bs[0][0][lk+2][lr]=s0.z; Bs[0][0][lk+3][lr]=s0.w;
        Bs[0][1][lk+0][lr]=s1.x; Bs[0][1][lk+1][lr]=s1.y; Bs[0][1][lk+2][lr]=s1.z; Bs[0][1][lk+3][lr]=s1.w;
        Bs[0][2][lk+0][lr]=s2.x; Bs[0][2][lk+1][lr]=s2.y; Bs[0][2][lk+2][lr]=s2.z; Bs[0][2][lk+3][lr]=s2.w;
    }
    __syncthreads();

    ull acc[3][4][2];
#pragma unroll
    for (int w = 0; w < 3; w++)
#pragma unroll
        for (int i = 0; i < 4; i++) { acc[w][i][0] = 0ull; acc[w][i][1] = 0ull; }

    for (int kt = 0; kt < 16; kt++) {
        const int cur = kt & 1;
        if (kt < 15) {
            sa = Ap[4*(kt+1)]; s0 = W0p[4*(kt+1)]; s1 = W1p[4*(kt+1)]; s2 = W2p[4*(kt+1)];
        }
#pragma unroll
        for (int kk = 0; kk < 16; kk++) {
            ull bv[3][2];
#pragma unroll
            for (int w = 0; w < 3; w++) {
                bv[w][0] = *(const ull*)&Bs[cur][w][kk][tx*4];
                bv[w][1] = *(const ull*)&Bs[cur][w][kk][tx*4+2];
            }
#pragma unroll
            for (int i = 0; i < 4; i++) {
                float a = As[cur][kk][ty*4+i];
                ull ad = pk2(a, a);
#pragma unroll
                for (int w = 0; w < 3; w++) {
                    acc[w][i][0] = ffma2(ad, bv[w][0], acc[w][i][0]);
                    acc[w][i][1] = ffma2(ad, bv[w][1], acc[w][i][1]);
                }
            }
        }
        if (kt < 15) {
            const int nb = cur ^ 1;
            As[nb][lk+0][lr]=sa.x; As[nb][lk+1][lr]=sa.y; As[nb][lk+2][lr]=sa.z; As[nb][lk+3][lr]=sa.w;
            Bs[nb][0][lk+0][lr]=s0.x; Bs[nb][0][lk+1][lr]=s0.y; Bs[nb][0][lk+2][lr]=s0.z; Bs[nb][0][lk+3][lr]=s0.w;
            Bs[nb][1][lk+0][lr]=s1.x; Bs[nb][1][lk+1][lr]=s1.y; Bs[nb][1][lk+2][lr]=s1.z; Bs[nb][1][lk+3][lr]=s1.w;
            Bs[nb][2][lk+0][lr]=s2.x; Bs[nb][2][lk+1][lr]=s2.y; Bs[nb][2][lk+2][lr]=s2.z; Bs[nb][2][lk+3][lr]=s2.w;
        }
        __syncthreads();
    }

    const float* bias[3] = {b0, b1, b2};
    float*       outp[3] = {o0, o1, o2};
#pragma unroll
    for (int w = 0; w < 3; w++)
#pragma unroll
        for (int i = 0; i < 4; i++) {
            int m = m0 + ty*4 + i;
#pragma unroll
            for (int p = 0; p < 2; p++) {
                int n = n0 + tx*4 + p*2;
                float2 v = upk2(acc[w][i][p]);
                v.x += bias[w][n]; v.y += bias[w][n+1];
                *(float2*)&outp[w][(size_t)m * C_ + n] = v;
            }
        }
}

// ---------------------------------------------------------------------------
// k transpose: g_k [b][tok][h*32+d] -> g_kt [b][h][d][tok]
// ---------------------------------------------------------------------------
__global__ void __launch_bounds__(256) kt_transpose() {
    __shared__ float tile[32][33];
    const int t  = threadIdx.x;
    const int t0 = blockIdx.x * 32;
    const int h  = blockIdx.y;
    const int b  = blockIdx.z;
    {
        int r = t >> 3, c4 = (t & 7) * 4;
        float4 v = *(const float4*)&g_k[((size_t)(b * N_ + t0 + r)) * C_ + h * D_ + c4];
        tile[r][c4+0] = v.x; tile[r][c4+1] = v.y;
        tile[r][c4+2] = v.z; tile[r][c4+3] = v.w;
    }
    __syncthreads();
    {
        int d = t >> 3, tok4 = (t & 7) * 4;
        float4 v;
        v.x = tile[tok4+0][d]; v.y = tile[tok4+1][d];
        v.z = tile[tok4+2][d]; v.w = tile[tok4+3][d];
        *(float4*)&g_kt[(((size_t)b * H_ + h) * D_ + d) * N_ + t0 + tok4] = v;
    }
}

// ---------------------------------------------------------------------------
// Output GEMM with bias + residual — FFMA2 (proven)
// ---------------------------------------------------------------------------
__global__ void __launch_bounds__(256) gemm_o(const float* __restrict__ A,
                                              const float* __restrict__ W,
                                              const float* __restrict__ bias,
                                              const float* __restrict__ res,
                                              float* __restrict__ out) {
    __shared__ float As[2][16][64];
    __shared__ float Bs[2][16][64];
    const int t  = threadIdx.x;
    const int m0 = blockIdx.y * 64;
    const int n0 = blockIdx.x * 64;
    const int ty = t >> 4, tx = t & 15;
    const int lr = t >> 2;
    const int lk = (t & 3) * 4;

    const float4* Ap = (const float4*)&A[(size_t)(m0 + lr) * C_ + lk];
    const float4* Wp = (const float4*)&W[(size_t)(n0 + lr) * C_ + lk];

    float4 sa = Ap[0], sw = Wp[0];
    As[0][lk+0][lr]=sa.x; As[0][lk+1][lr]=sa.y; As[0][lk+2][lr]=sa.z; As[0][lk+3][lr]=sa.w;
    Bs[0][lk+0][lr]=sw.x; Bs[0][lk+1][lr]=sw.y; Bs[0][lk+2][lr]=sw.z; Bs[0][lk+3][lr]=sw.w;
    __syncthreads();

    ull acc[4][2];
#pragma unroll
    for (int i = 0; i < 4; i++) { acc[i][0] = 0ull; acc[i][1] = 0ull; }

    for (int kt = 0; kt < 16; kt++) {
        const int cur = kt & 1;
        if (kt < 15) { sa = Ap[4*(kt+1)]; sw = Wp[4*(kt+1)]; }
#pragma unroll
        for (int kk = 0; kk < 16; kk++) {
            ull bv0 = *(const ull*)&Bs[cur][kk][tx*4];
            ull bv1 = *(const ull*)&Bs[cur][kk][tx*4+2];
#pragma unroll
            for (int i = 0; i < 4; i++) {
                float a = As[cur][kk][ty*4+i];
                ull ad = pk2(a, a);
                acc[i][0] = ffma2(ad, bv0, acc[i][0]);
                acc[i][1] = ffma2(ad, bv1, acc[i][1]);
            }
        }
        if (kt < 15) {
            const int nb = cur ^ 1;
            As[nb][lk+0][lr]=sa.x; As[nb][lk+1][lr]=sa.y; As[nb][lk+2][lr]=sa.z; As[nb][lk+3][lr]=sa.w;
            Bs[nb][lk+0][lr]=sw.x; Bs[nb][lk+1][lr]=sw.y; Bs[nb][lk+2][lr]=sw.z; Bs[nb][lk+3][lr]=sw.w;
        }
        __syncthreads();
    }
#pragma unroll
    for (int i = 0; i < 4; i++) {
        int m = m0 + ty*4 + i;
#pragma unroll
        for (int p = 0; p < 2; p++) {
            int n = n0 + tx*4 + p*2;
            float2 v = upk2(acc[i][p]);
            v.x += bias[n]   + res[(size_t)m * C_ + n];
            v.y += bias[n+1] + res[(size_t)m * C_ + n + 1];
            *(float2*)&out[(size_t)m * C_ + n] = v;
        }
    }
}

// ---------------------------------------------------------------------------
// column max of mask
// ---------------------------------------------------------------------------
__global__ void __launch_bounds__(256) cmax_init() {
    int i = blockIdx.x * 256 + threadIdx.x;
    if (i < B_ * N_) g_cmax[i] = 0;
}
__global__ void __launch_bounds__(256) cmax_k(const float* __restrict__ mask) {
    int q = blockIdx.x * 256 + threadIdx.x;
    int b = blockIdx.z;
    const float* p = mask + (size_t)b * N_ * N_ + (size_t)(blockIdx.y * 256) * N_ + q;
    float m = 0.f;
#pragma unroll 8
    for (int k = 0; k < 256; k++) m = fmaxf(m, p[(size_t)k * N_]);
    atomicMax(&g_cmax[b * N_ + q], __float_as_int(m));
}

// ---------------------------------------------------------------------------
// fused attention: one CTA = (h, 16 q rows). 512 threads (16 warps).
// P1/P4 on tensor cores (mma.sync m16n8k8 tf32).
// ---------------------------------------------------------------------------
constexpr int PS    = 2052;              // probs row stride
constexpr int KTW   = 512;               // k-tile width
constexpr int KSS   = 520;               // k^T smem row stride
constexpr int VSTR  = 40;                // v smem row stride (bank-clean for mma B)
constexpr int QFS   = 36;                // q smem row stride (bank-clean for mma A)
constexpr int XSTR  = 36;                // x staging row stride
constexpr int XWARP = 576;               // x staging per-warp stride (16*36)
constexpr int OFF_KV = 16 * PS;          // 32832
constexpr int KVSZ   = KTW * VSTR;       // 20480 (v tile; >= k tile 32*520, >= 16*576)
constexpr int OFF_QF = OFF_KV + KVSZ;    // 53312
constexpr int OFF_ST = OFF_QF + 16*QFS;  // 53888
constexpr int SM_FLOATS = OFF_ST + 32 + 256;  // invs16+comb16+wpart256 = 54176
constexpr int SM_BYTES  = SM_FLOATS * 4;      // 216704 B

__global__ void __launch_bounds__(512, 1) attn_k(const float* __restrict__ mask,
                                                 float* __restrict__ attn_out, int b) {
    extern __shared__ float sm[];
    float* probs = sm;
    float* kvf   = sm + OFF_KV;
    float* qf    = sm + OFF_QF;
    float* invs  = sm + OFF_ST;         // [16]
    float* comb  = invs + 16;           // [16]
    float* wpart = comb + 16;           // [16 warps][16 rows]

    const int t    = threadIdx.x;
    const int wid  = t >> 5, lane = t & 31;
    const int g    = lane >> 2, tq = lane & 3;
    const int q0   = blockIdx.x * 16;
    const int h    = blockIdx.y;

    const float* qsrc  = g_q  + ((size_t)b * N_ + q0) * C_ + h * D_;
    const float* ktsrc = g_kt + ((size_t)b * H_ + h) * D_ * N_;
    const float* vsrc  = g_v  + (size_t)b * N_ * C_ + h * D_;

    // ---- q tile: tf32(q*scale), stride 36 ----
    {
        int qi = t >> 5, d = t & 31;
        qf[qi * QFS + d] = tf32r(qsrc[(size_t)qi * C_ + d] * SCALE_L2);
    }

    float4 st[8];
    // prologue: k^T tile 0 (g_kt [d][tok] straight copy + tf32 round)
#pragma unroll
    for (int i = 0; i < 8; i++) {
        int idx = t + 512 * i, d = idx >> 7, c4 = (idx & 127) * 4;
        st[i] = *(const float4*)&ktsrc[(size_t)d * N_ + c4];
    }
    __syncthreads();   // qf visible
#pragma unroll
    for (int i = 0; i < 8; i++) {
        int idx = t + 512 * i, d = idx >> 7, c4 = (idx & 127) * 4;
        float* dst = &kvf[d * KSS + c4];
        dst[0] = tf32r(st[i].x); dst[1] = tf32r(st[i].y);
        dst[2] = tf32r(st[i].z); dst[3] = tf32r(st[i].w);
    }
    __syncthreads();

    // ---- P1: S = QK^T on tensor cores, + exp2 + rowsum in registers ----
    const int nb = wid * 32;            // this warp's 32 keys within tile
    float rs_lo = 0.f, rs_hi = 0.f;
    for (int kt = 0; kt < 4; kt++) {
        if (kt < 3) {
            const int k0n = (kt + 1) * KTW;
#pragma unroll
            for (int i = 0; i < 8; i++) {
                int idx = t + 512 * i, d = idx >> 7, c4 = (idx & 127) * 4;
                st[i] = *(const float4*)&ktsrc[(size_t)d * N_ + k0n + c4];
            }
        }
        float4 acc[4];
#pragma unroll
        for (int nt = 0; nt < 4; nt++) acc[nt] = make_float4(0.f, 0.f, 0.f, 0.f);
#pragma unroll
        for (int kc = 0; kc < 32; kc += 8) {
            uint32_t a0 = fb(qf[ g      * QFS + kc + tq]);
            uint32_t a1 = fb(qf[(g + 8) * QFS + kc + tq]);
            uint32_t a2 = fb(qf[ g      * QFS + kc + tq + 4]);
            uint32_t a3 = fb(qf[(g + 8) * QFS + kc + tq + 4]);
#pragma unroll
            for (int nt = 0; nt < 4; nt++) {
                uint32_t b0 = fb(kvf[(kc + tq)     * KSS + nb + 8*nt + g]);
                uint32_t b1 = fb(kvf[(kc + tq + 4) * KSS + nb + 8*nt + g]);
                mma8(acc[nt], a0, a1, a2, a3, b0, b1);
            }
        }
        const int k0 = kt * KTW;
#pragma unroll
        for (int nt = 0; nt < 4; nt++) {
            float e0 = ex2f(acc[nt].x), e1 = ex2f(acc[nt].y);
            float e2 = ex2f(acc[nt].z), e3 = ex2f(acc[nt].w);
            rs_lo += e0 + e1; rs_hi += e2 + e3;
            int col = k0 + nb + 8*nt + 2*tq;
            *(float2*)&probs[(size_t) g      * PS + col] = make_float2(e0, e1);
            *(float2*)&probs[(size_t)(g + 8) * PS + col] = make_float2(e2, e3);
        }
        __syncthreads();
        if (kt < 3) {
#pragma unroll
            for (int i = 0; i < 8; i++) {
                int idx = t + 512 * i, d = idx >> 7, c4 = (idx & 127) * 4;
                float* dst = &kvf[d * KSS + c4];
                dst[0] = tf32r(st[i].x); dst[1] = tf32r(st[i].y);
                dst[2] = tf32r(st[i].z); dst[3] = tf32r(st[i].w);
            }
            __syncthreads();
        }
    }

    // rowsum: reduce over the 4-lane quad (cols), then across warps
    rs_lo += __shfl_xor_sync(0xffffffffu, rs_lo, 1);
    rs_lo += __shfl_xor_sync(0xffffffffu, rs_lo, 2);
    rs_hi += __shfl_xor_sync(0xffffffffu, rs_hi, 1);
    rs_hi += __shfl_xor_sync(0xffffffffu, rs_hi, 2);
    if (tq == 0) {
        wpart[wid * 16 + g]     = rs_lo;
        wpart[wid * 16 + g + 8] = rs_hi;
    }
    // stage v tile 0 early (hide gmem latency behind stats + P3)
#pragma unroll
    for (int i = 0; i < 8; i++)
        st[i] = *(const float4*)&vsrc[(size_t)t * C_ + i * 4];
    __syncthreads();
    if (t < 16) {
        float s = 0.f;
#pragma unroll
        for (int w = 0; w < 16; w++) s += wpart[w * 16 + t];
        float iv = 1.0f / s;
        invs[t] = iv;
        comb[t] = iv / __int_as_float(g_cmax[b * N_ + q0 + t]);
    }
    __syncthreads();

    // ---- P3a: attn_vis = e * invsum, float4 coalesced ----
    {
        float4* ao4 = (float4*)(attn_out + (((size_t)b * H_ + h) * N_ + q0) * N_);
        const float4* p4 = (const float4*)probs;
#pragma unroll 4
        for (int i = 0; i < 16; i++) {
            int idx = t + 512 * i;
            int qi = idx >> 9, m = idx & 511;
            float4 v = p4[(size_t)qi * (PS/4) + m];
            float s = invs[qi];
            v.x *= s; v.y *= s; v.z *= s; v.w *= s;
            ao4[(size_t)qi * 512 + m] = v;
        }
    }
    __syncthreads();
    // ---- P3b: probs *= invsum * mask/colmax ----
    {
        const float* mk = mask + (size_t)b * N_ * N_ + q0;
#pragma unroll 4
        for (int i = 0; i < 64; i++) {
            int idx = t + 512 * i;
            int qi = idx & 15, k = idx >> 4;
            probs[(size_t)qi * PS + k] *= comb[qi] * mk[(size_t)k * N_ + qi];
        }
    }
    // store v tile 0 (tf32-rounded), row stride VSTR
#pragma unroll
    for (int i = 0; i < 8; i++) {
        float* dst = &kvf[t * VSTR + 4 * i];
        dst[0] = tf32r(st[i].x); dst[1] = tf32r(st[i].y);
        dst[2] = tf32r(st[i].z); dst[3] = tf32r(st[i].w);
    }
    __syncthreads();

    // ---- P4: X = P @ V on tensor cores, split-K over 16 warps ----
    float4 acc2[4];
#pragma unroll
    for (int nt = 0; nt < 4; nt++) acc2[nt] = make_float4(0.f, 0.f, 0.f, 0.f);

    for (int kt = 0; kt < 4; kt++) {
        if (kt < 3) {
            const int k0n = (kt + 1) * KTW;
#pragma unroll
            for (int i = 0; i < 8; i++)
                st[i] = *(const float4*)&vsrc[(size_t)(k0n + t) * C_ + i * 4];
        }
        const int klo = wid * 32, ka0 = kt * KTW + klo;
#pragma unroll
        for (int kc = 0; kc < 4; kc++) {
            const int kb = ka0 + kc * 8;
            uint32_t a0 = fb(tf32r(probs[(size_t) g      * PS + kb + tq]));
            uint32_t a1 = fb(tf32r(probs[(size_t)(g + 8) * PS + kb + tq]));
            uint32_t a2 = fb(tf32r(probs[(size_t) g      * PS + kb + tq + 4]));
            uint32_t a3 = fb(tf32r(probs[(size_t)(g + 8) * PS + kb + tq + 4]));
            const int kl = klo + kc * 8;
#pragma unroll
            for (int nt = 0; nt < 4; nt++) {
                uint32_t b0 = fb(kvf[(kl + tq)     * VSTR + 8*nt + g]);
                uint32_t b1 = fb(kvf[(kl + tq + 4) * VSTR + 8*nt + g]);
                mma8(acc2[nt], a0, a1, a2, a3, b0, b1);
            }
        }
        __syncthreads();
        if (kt < 3) {
#pragma unroll
            for (int i = 0; i < 8; i++) {
                float* dst = &kvf[t * VSTR + 4 * i];
                dst[0] = tf32r(st[i].x); dst[1] = tf32r(st[i].y);
                dst[2] = tf32r(st[i].z); dst[3] = tf32r(st[i].w);
            }
            __syncthreads();
        }
    }
    // stage per-warp X (16x32, stride 36) and reduce across 16 warps
#pragma unroll
    for (int nt = 0; nt < 4; nt++) {
        int d = 8 * nt + 2 * tq;
        *(float2*)&kvf[wid * XWARP +  g      * XSTR + d] = make_float2(acc2[nt].x, acc2[nt].y);
        *(float2*)&kvf[wid * XWARP + (g + 8) * XSTR + d] = make_float2(acc2[nt].z, acc2[nt].w);
    }
    __syncthreads();
    {
        int r = t >> 5, d = t & 31;
        float s = 0.f;
#pragma unroll
        for (int w2 = 0; w2 < 16; w2++) s += kvf[w2 * XWARP + r * XSTR + d];
        g_x[((size_t)b * N_ + q0 + r) * C_ + h * D_ + d] = s;
    }
}

// ---------------------------------------------------------------------------
extern "C" void kernel_launch(void* const* d_in, const int* in_sizes, int n_in,
                              void* d_out, int out_size) {
    (void)in_sizes; (void)n_in; (void)out_size;
    const float* query = (const float*)d_in[0];
    const float* mask  = (const float*)d_in[1];
    const float* Wq    = (const float*)d_in[2];
    const float* bq    = (const float*)d_in[3];
    const float* Wk    = (const float*)d_in[4];
    const float* bk    = (const float*)d_in[5];
    const float* Wv    = (const float*)d_in[6];
    const float* bv    = (const float*)d_in[7];
    const float* Wo    = (const float*)d_in[8];
    const float* bo    = (const float*)d_in[9];

    float* out      = (float*)d_out;
    float* attn_out = out + (size_t)B_ * N_ * C_;

    void* p;
    cudaGetSymbolAddress(&p, g_q);   float* gq = (float*)p;
    cudaGetSymbolAddress(&p, g_k);   float* gk = (float*)p;
    cudaGetSymbolAddress(&p, g_v);   float* gv = (float*)p;
    cudaGetSymbolAddress(&p, g_x);   float* gx = (float*)p;

    cudaFuncSetAttribute(attn_k, cudaFuncAttributeMaxDynamicSharedMemorySize, SM_BYTES);

    dim3 gg(4, 128);
    gemm_qkv<<<gg, 256>>>(query, Wq, bq, gq, Wk, bk, gk, Wv, bv, gv);
    kt_transpose<<<dim3(N_ / 32, H_, B_), 256>>>();

    cmax_init<<<(B_ * N_ + 255) / 256, 256>>>();
    cmax_k<<<dim3(8, 8, 4), 256>>>(mask);

    for (int b = 0; b < B_; b++)
        attn_k<<<dim3(N_ / 16, H_), 512, SM_BYTES>>>(mask, attn_out, b);

    gemm_o<<<gg, 256>>>(gx, Wo, bo, query, out);
}

// round 12
// speedup vs baseline: 1.5593x; 1.5593x over previous
#include <cuda_runtime.h>
#include <cstdint>

// ---------------------------------------------------------------------------
// MaskMultiheadAttention  (B=4, N=2048, C=256, H=8, Dh=32)
// out = (query + proj_o(attn_masked @ V), softmax(QK^T*scale))
// d_out layout: [out_query (B*N*C floats)] [attn_vis (B*H*N*N floats)]
// Attention inner GEMMs via mma.sync tf32; K/V tiles in natural layout.
// ---------------------------------------------------------------------------

constexpr int B_ = 4, N_ = 2048, C_ = 256, H_ = 8, D_ = 32;
constexpr float SCALE_L2 = 0.17677669529663687f * 1.4426950408889634f;

__device__ float g_q [B_ * N_ * C_];
__device__ float g_k [B_ * N_ * C_];
__device__ float g_v [B_ * N_ * C_];
__device__ float g_x [B_ * N_ * C_];
__device__ float g_mt[(size_t)B_ * N_ * N_];   // mask^T/colmax: [b][q][k]
__device__ int   g_cmax[B_ * N_];

#define DEV_INLINE __device__ __forceinline__
typedef unsigned long long ull;

DEV_INLINE ull pk2(float lo, float hi) {
    ull r; asm("mov.b64 %0, {%1, %2};" : "=l"(r) : "f"(lo), "f"(hi)); return r;
}
DEV_INLINE float2 upk2(ull v) {
    float2 f; asm("mov.b64 {%0, %1}, %2;" : "=f"(f.x), "=f"(f.y) : "l"(v)); return f;
}
DEV_INLINE ull ffma2(ull a, ull b, ull c) {
    ull d; asm("fma.rn.f32x2 %0, %1, %2, %3;" : "=l"(d) : "l"(a), "l"(b), "l"(c)); return d;
}
DEV_INLINE float ex2f(float x) {
    float y; asm("ex2.approx.ftz.f32 %0, %1;" : "=f"(y) : "f"(x)); return y;
}
DEV_INLINE uint32_t fb(float x) { return __float_as_uint(x); }

// m16n8k8 tf32 MMA, row.col. Per-lane (g=lane>>2, tq=lane&3):
//  A: a0=(g,tq) a1=(g+8,tq) a2=(g,tq+4) a3=(g+8,tq+4)
//  B: b0=(k=tq,n=g) b1=(k=tq+4,n=g)
//  D: d0=(g,2tq) d1=(g,2tq+1) d2=(g+8,2tq) d3=(g+8,2tq+1)
DEV_INLINE void mma8(float4& d, uint32_t a0, uint32_t a1, uint32_t a2, uint32_t a3,
                     uint32_t b0, uint32_t b1) {
    asm volatile("mma.sync.aligned.m16n8k8.row.col.f32.tf32.tf32.f32 "
                 "{%0,%1,%2,%3}, {%4,%5,%6,%7}, {%8,%9}, {%0,%1,%2,%3};"
                 : "+f"(d.x), "+f"(d.y), "+f"(d.z), "+f"(d.w)
                 : "r"(a0), "r"(a1), "r"(a2), "r"(a3), "r"(b0), "r"(b1));
}

// ---------------------------------------------------------------------------
// QKV GEMM (NT, fused 3 outputs) — FFMA2 (proven)
// ---------------------------------------------------------------------------
__global__ void __launch_bounds__(256) gemm_qkv(
    const float* __restrict__ A,
    const float* __restrict__ W0, const float* __restrict__ b0, float* __restrict__ o0,
    const float* __restrict__ W1, const float* __restrict__ b1, float* __restrict__ o1,
    const float* __restrict__ W2, const float* __restrict__ b2, float* __restrict__ o2) {
    __shared__ float As[2][16][64];
    __shared__ float Bs[2][3][16][64];
    const int t  = threadIdx.x;
    const int m0 = blockIdx.y * 64;
    const int n0 = blockIdx.x * 64;
    const int ty = t >> 4, tx = t & 15;
    const int lr = t >> 2;
    const int lk = (t & 3) * 4;

    const float4* Ap  = (const float4*)&A [(size_t)(m0 + lr) * C_ + lk];
    const float4* W0p = (const float4*)&W0[(size_t)(n0 + lr) * C_ + lk];
    const float4* W1p = (const float4*)&W1[(size_t)(n0 + lr) * C_ + lk];
    const float4* W2p = (const float4*)&W2[(size_t)(n0 + lr) * C_ + lk];

    float4 sa = Ap[0], s0 = W0p[0], s1 = W1p[0], s2 = W2p[0];
    {
        As[0][lk+0][lr]=sa.x; As[0][lk+1][lr]=sa.y; As[0][lk+2][lr]=sa.z; As[0][lk+3][lr]=sa.w;
        Bs[0][0][lk+0][lr]=s0.x; Bs[0][0][lk+1][lr]=s0.y; Bs[0][0][lk+2][lr]=s0.z; Bs[0][0][lk+3][lr]=s0.w;
        Bs[0][1][lk+0][lr]=s1.x; Bs[0][1][lk+1][lr]=s1.y; Bs[0][1][lk+2][lr]=s1.z; Bs[0][1][lk+3][lr]=s1.w;
        Bs[0][2][lk+0][lr]=s2.x; Bs[0][2][lk+1][lr]=s2.y; Bs[0][2][lk+2][lr]=s2.z; Bs[0][2][lk+3][lr]=s2.w;
    }
    __syncthreads();

    ull acc[3][4][2];
#pragma unroll
    for (int w = 0; w < 3; w++)
#pragma unroll
        for (int i = 0; i < 4; i++) { acc[w][i][0] = 0ull; acc[w][i][1] = 0ull; }

    for (int kt = 0; kt < 16; kt++) {
        const int cur = kt & 1;
        if (kt < 15) {
            sa = Ap[4*(kt+1)]; s0 = W0p[4*(kt+1)]; s1 = W1p[4*(kt+1)]; s2 = W2p[4*(kt+1)];
        }
#pragma unroll
        for (int kk = 0; kk < 16; kk++) {
            ull bv[3][2];
#pragma unroll
            for (int w = 0; w < 3; w++) {
                bv[w][0] = *(const ull*)&Bs[cur][w][kk][tx*4];
                bv[w][1] = *(const ull*)&Bs[cur][w][kk][tx*4+2];
            }
#pragma unroll
            for (int i = 0; i < 4; i++) {
                float a = As[cur][kk][ty*4+i];
                ull ad = pk2(a, a);
#pragma unroll
                for (int w = 0; w < 3; w++) {
                    acc[w][i][0] = ffma2(ad, bv[w][0], acc[w][i][0]);
                    acc[w][i][1] = ffma2(ad, bv[w][1], acc[w][i][1]);
                }
            }
        }
        if (kt < 15) {
            const int nb = cur ^ 1;
            As[nb][lk+0][lr]=sa.x; As[nb][lk+1][lr]=sa.y; As[nb][lk+2][lr]=sa.z; As[nb][lk+3][lr]=sa.w;
            Bs[nb][0][lk+0][lr]=s0.x; Bs[nb][0][lk+1][lr]=s0.y; Bs[nb][0][lk+2][lr]=s0.z; Bs[nb][0][lk+3][lr]=s0.w;
            Bs[nb][1][lk+0][lr]=s1.x; Bs[nb][1][lk+1][lr]=s1.y; Bs[nb][1][lk+2][lr]=s1.z; Bs[nb][1][lk+3][lr]=s1.w;
            Bs[nb][2][lk+0][lr]=s2.x; Bs[nb][2][lk+1][lr]=s2.y; Bs[nb][2][lk+2][lr]=s2.z; Bs[nb][2][lk+3][lr]=s2.w;
        }
        __syncthreads();
    }

    const float* bias[3] = {b0, b1, b2};
    float*       outp[3] = {o0, o1, o2};
#pragma unroll
    for (int w = 0; w < 3; w++)
#pragma unroll
        for (int i = 0; i < 4; i++) {
            int m = m0 + ty*4 + i;
#pragma unroll
            for (int p = 0; p < 2; p++) {
                int n = n0 + tx*4 + p*2;
                float2 v = upk2(acc[w][i][p]);
                v.x += bias[w][n]; v.y += bias[w][n+1];
                *(float2*)&outp[w][(size_t)m * C_ + n] = v;
            }
        }
}

// ---------------------------------------------------------------------------
// Output GEMM with bias + residual — FFMA2 (proven)
// ---------------------------------------------------------------------------
__global__ void __launch_bounds__(256) gemm_o(const float* __restrict__ A,
                                              const float* __restrict__ W,
                                              const float* __restrict__ bias,
                                              const float* __restrict__ res,
                                              float* __restrict__ out) {
    __shared__ float As[2][16][64];
    __shared__ float Bs[2][16][64];
    const int t  = threadIdx.x;
    const int m0 = blockIdx.y * 64;
    const int n0 = blockIdx.x * 64;
    const int ty = t >> 4, tx = t & 15;
    const int lr = t >> 2;
    const int lk = (t & 3) * 4;

    const float4* Ap = (const float4*)&A[(size_t)(m0 + lr) * C_ + lk];
    const float4* Wp = (const float4*)&W[(size_t)(n0 + lr) * C_ + lk];

    float4 sa = Ap[0], sw = Wp[0];
    As[0][lk+0][lr]=sa.x; As[0][lk+1][lr]=sa.y; As[0][lk+2][lr]=sa.z; As[0][lk+3][lr]=sa.w;
    Bs[0][lk+0][lr]=sw.x; Bs[0][lk+1][lr]=sw.y; Bs[0][lk+2][lr]=sw.z; Bs[0][lk+3][lr]=sw.w;
    __syncthreads();

    ull acc[4][2];
#pragma unroll
    for (int i = 0; i < 4; i++) { acc[i][0] = 0ull; acc[i][1] = 0ull; }

    for (int kt = 0; kt < 16; kt++) {
        const int cur = kt & 1;
        if (kt < 15) { sa = Ap[4*(kt+1)]; sw = Wp[4*(kt+1)]; }
#pragma unroll
        for (int kk = 0; kk < 16; kk++) {
            ull bv0 = *(const ull*)&Bs[cur][kk][tx*4];
            ull bv1 = *(const ull*)&Bs[cur][kk][tx*4+2];
#pragma unroll
            for (int i = 0; i < 4; i++) {
                float a = As[cur][kk][ty*4+i];
                ull ad = pk2(a, a);
                acc[i][0] = ffma2(ad, bv0, acc[i][0]);
                acc[i][1] = ffma2(ad, bv1, acc[i][1]);
            }
        }
        if (kt < 15) {
            const int nb = cur ^ 1;
            As[nb][lk+0][lr]=sa.x; As[nb][lk+1][lr]=sa.y; As[nb][lk+2][lr]=sa.z; As[nb][lk+3][lr]=sa.w;
            Bs[nb][lk+0][lr]=sw.x; Bs[nb][lk+1][lr]=sw.y; Bs[nb][lk+2][lr]=sw.z; Bs[nb][lk+3][lr]=sw.w;
        }
        __syncthreads();
    }
#pragma unroll
    for (int i = 0; i < 4; i++) {
        int m = m0 + ty*4 + i;
#pragma unroll
        for (int p = 0; p < 2; p++) {
            int n = n0 + tx*4 + p*2;
            float2 v = upk2(acc[i][p]);
            v.x += bias[n]   + res[(size_t)m * C_ + n];
            v.y += bias[n+1] + res[(size_t)m * C_ + n + 1];
            *(float2*)&out[(size_t)m * C_ + n] = v;
        }
    }
}

// ---------------------------------------------------------------------------
// mask: column max, then normalized transpose g_mt[b][q][k] = mask[b][k][q]/cmax
// ---------------------------------------------------------------------------
__global__ void __launch_bounds__(256) cmax_init() {
    int i = blockIdx.x * 256 + threadIdx.x;
    if (i < B_ * N_) g_cmax[i] = 0;
}
__global__ void __launch_bounds__(256) cmax_k(const float* __restrict__ mask) {
    int q = blockIdx.x * 256 + threadIdx.x;
    int b = blockIdx.z;
    const float* p = mask + (size_t)b * N_ * N_ + (size_t)(blockIdx.y * 256) * N_ + q;
    float m = 0.f;
#pragma unroll 8
    for (int k = 0; k < 256; k++) m = fmaxf(m, p[(size_t)k * N_]);
    atomicMax(&g_cmax[b * N_ + q], __float_as_int(m));
}
__global__ void __launch_bounds__(256) mt_k(const float* __restrict__ mask) {
    __shared__ float tl[64][65];
    const int t  = threadIdx.x;
    const int k0 = blockIdx.x * 64, qq0 = blockIdx.y * 64, b = blockIdx.z;
#pragma unroll
    for (int i = 0; i < 16; i++) {
        int idx = t + 256 * i;
        int r = idx >> 6, c = idx & 63;
        tl[r][c] = mask[((size_t)(b * N_ + k0 + r)) * N_ + qq0 + c];
    }
    __syncthreads();
#pragma unroll
    for (int i = 0; i < 16; i++) {
        int idx = t + 256 * i;
        int r = idx >> 6, c = idx & 63;
        float ic = 1.0f / __int_as_float(g_cmax[b * N_ + qq0 + r]);
        g_mt[((size_t)(b * N_ + qq0 + r)) * N_ + k0 + c] = tl[c][r] * ic;
    }
}

// ---------------------------------------------------------------------------
// fused attention: one CTA = (b, h, 16 q rows). 512 threads (16 warps).
// mma.sync tf32 for QK^T and PV; K/V staged in natural [tok][d] layout.
// ---------------------------------------------------------------------------
constexpr int PS    = 2052;              // probs row stride (floats)
constexpr int KTW   = 512;               // keys per tile
constexpr int KVS   = 36;                // K/V smem row stride
constexpr int QFS   = 36;                // q smem row stride
constexpr int XSTR  = 36;                // x staging row stride
constexpr int XWARP = 576;               // per-warp x staging (16*36)
constexpr int OFF_KV = 16 * PS;          // 32832
constexpr int KVSZ   = KTW * KVS;        // 18432
constexpr int OFF_QF = OFF_KV + KVSZ;    // 51264
constexpr int OFF_ST = OFF_QF + 16*QFS;  // 51840
constexpr int SM_FLOATS = OFF_ST + 16 + 256;  // invs16 + wpart256 = 52112
constexpr int SM_BYTES  = SM_FLOATS * 4;      // 208448 B

__global__ void __launch_bounds__(512, 1) attn_k(float* __restrict__ attn_out) {
    extern __shared__ float sm[];
    float* probs = sm;
    float* kvf   = sm + OFF_KV;
    float* qf    = sm + OFF_QF;
    float* invs  = sm + OFF_ST;         // [16]
    float* wpart = invs + 16;           // [16 warps][16 rows]

    const int t    = threadIdx.x;
    const int wid  = t >> 5, lane = t & 31;
    const int g    = lane >> 2, tq = lane & 3;
    const int q0   = blockIdx.x * 16;
    const int h    = blockIdx.y;
    const int b    = blockIdx.z;

    const float* qsrc = g_q + ((size_t)b * N_ + q0) * C_ + h * D_;
    const float* ksrc = g_k + (size_t)b * N_ * C_ + h * D_;
    const float* vsrc = g_v + (size_t)b * N_ * C_ + h * D_;

    // ---- q tile: q*scale, stride 36 ----
    {
        int qi = t >> 5, d = t & 31;
        qf[qi * QFS + d] = qsrc[(size_t)qi * C_ + d] * SCALE_L2;
    }

    float4 st[8];
    // prologue: K tile 0, coalesced (8 lanes per token row)
#pragma unroll
    for (int i = 0; i < 8; i++) {
        int idx = t + 512 * i, kk = idx >> 3, j = idx & 7;
        st[i] = *(const float4*)&ksrc[(size_t)kk * C_ + j * 4];
    }
    __syncthreads();   // qf visible
#pragma unroll
    for (int i = 0; i < 8; i++) {
        int idx = t + 512 * i, kk = idx >> 3, j = idx & 7;
        *(float4*)&kvf[kk * KVS + j * 4] = st[i];
    }
    __syncthreads();

    // ---- P1: S = QK^T (mma), exp2 + rowsum in registers ----
    const int nb = wid * 32;            // this warp's keys within tile
    float rs_lo = 0.f, rs_hi = 0.f;
    for (int kt = 0; kt < 4; kt++) {
        if (kt < 3) {
            const int k0n = (kt + 1) * KTW;
#pragma unroll
            for (int i = 0; i < 8; i++) {
                int idx = t + 512 * i, kk = idx >> 3, j = idx & 7;
                st[i] = *(const float4*)&ksrc[(size_t)(k0n + kk) * C_ + j * 4];
            }
        }
        float4 acc[4];
#pragma unroll
        for (int nt = 0; nt < 4; nt++) acc[nt] = make_float4(0.f, 0.f, 0.f, 0.f);
#pragma unroll
        for (int kc = 0; kc < 32; kc += 8) {
            uint32_t a0 = fb(qf[ g      * QFS + kc + tq]);
            uint32_t a1 = fb(qf[(g + 8) * QFS + kc + tq]);
            uint32_t a2 = fb(qf[ g      * QFS + kc + tq + 4]);
            uint32_t a3 = fb(qf[(g + 8) * QFS + kc + tq + 4]);
#pragma unroll
            for (int nt = 0; nt < 4; nt++) {
                const int tok = nb + 8*nt + g;
                uint32_t b0 = fb(kvf[tok * KVS + kc + tq]);
                uint32_t b1 = fb(kvf[tok * KVS + kc + tq + 4]);
                mma8(acc[nt], a0, a1, a2, a3, b0, b1);
            }
        }
        const int k0 = kt * KTW;
#pragma unroll
        for (int nt = 0; nt < 4; nt++) {
            float e0 = ex2f(acc[nt].x), e1 = ex2f(acc[nt].y);
            float e2 = ex2f(acc[nt].z), e3 = ex2f(acc[nt].w);
            rs_lo += e0 + e1; rs_hi += e2 + e3;
            int col = k0 + nb + 8*nt + 2*tq;
            *(float2*)&probs[(size_t) g      * PS + col] = make_float2(e0, e1);
            *(float2*)&probs[(size_t)(g + 8) * PS + col] = make_float2(e2, e3);
        }
        __syncthreads();
        if (kt < 3) {
#pragma unroll
            for (int i = 0; i < 8; i++) {
                int idx = t + 512 * i, kk = idx >> 3, j = idx & 7;
                *(float4*)&kvf[kk * KVS + j * 4] = st[i];
            }
            __syncthreads();
        }
    }

    // rowsum: quad reduce then cross-warp combine
    rs_lo += __shfl_xor_sync(0xffffffffu, rs_lo, 1);
    rs_lo += __shfl_xor_sync(0xffffffffu, rs_lo, 2);
    rs_hi += __shfl_xor_sync(0xffffffffu, rs_hi, 1);
    rs_hi += __shfl_xor_sync(0xffffffffu, rs_hi, 2);
    if (tq == 0) {
        wpart[wid * 16 + g]     = rs_lo;
        wpart[wid * 16 + g + 8] = rs_hi;
    }
    // stage V tile 0 (latency hidden behind stats + P3)
#pragma unroll
    for (int i = 0; i < 8; i++) {
        int idx = t + 512 * i, kk = idx >> 3, j = idx & 7;
        st[i] = *(const float4*)&vsrc[(size_t)kk * C_ + j * 4];
    }
    __syncthreads();
    if (t < 16) {
        float s = 0.f;
#pragma unroll
        for (int w = 0; w < 16; w++) s += wpart[w * 16 + t];
        invs[t] = 1.0f / s;
    }
    __syncthreads();
    // store V tile 0 (kvf free after P1)
#pragma unroll
    for (int i = 0; i < 8; i++) {
        int idx = t + 512 * i, kk = idx >> 3, j = idx & 7;
        *(float4*)&kvf[kk * KVS + j * 4] = st[i];
    }

    // ---- P3 merged: vis = e*invs (streaming store) ; probs = vis * g_mt ----
    {
        float4* ao4 = (float4*)(attn_out + (((size_t)b * H_ + h) * N_ + q0) * N_);
        const float4* mt4 = (const float4*)(g_mt + ((size_t)b * N_ + q0) * N_);
        float4* p4 = (float4*)probs;
#pragma unroll 4
        for (int i = 0; i < 16; i++) {
            int idx = t + 512 * i;
            int qi = idx >> 9, m = idx & 511;
            float4 v = p4[(size_t)qi * (PS/4) + m];
            float s = invs[qi];
            v.x *= s; v.y *= s; v.z *= s; v.w *= s;
            __stcs(&ao4[(size_t)qi * 512 + m], v);
            float4 mm = mt4[(size_t)qi * 512 + m];
            v.x *= mm.x; v.y *= mm.y; v.z *= mm.z; v.w *= mm.w;
            p4[(size_t)qi * (PS/4) + m] = v;
        }
    }
    __syncthreads();

    // ---- P4: X = P @ V (mma), split-K over 16 warps ----
    float4 acc2[4];
#pragma unroll
    for (int nt = 0; nt < 4; nt++) acc2[nt] = make_float4(0.f, 0.f, 0.f, 0.f);

    for (int kt = 0; kt < 4; kt++) {
        if (kt < 3) {
            const int k0n = (kt + 1) * KTW;
#pragma unroll
            for (int i = 0; i < 8; i++) {
                int idx = t + 512 * i, kk = idx >> 3, j = idx & 7;
                st[i] = *(const float4*)&vsrc[(size_t)(k0n + kk) * C_ + j * 4];
            }
        }
        const int klo = wid * 32, ka0 = kt * KTW + klo;
#pragma unroll
        for (int kc = 0; kc < 4; kc++) {
            const int kb = ka0 + kc * 8;
            uint32_t a0 = fb(probs[(size_t) g      * PS + kb + tq]);
            uint32_t a1 = fb(probs[(size_t)(g + 8) * PS + kb + tq]);
            uint32_t a2 = fb(probs[(size_t) g      * PS + kb + tq + 4]);
            uint32_t a3 = fb(probs[(size_t)(g + 8) * PS + kb + tq + 4]);
            const int kl = klo + kc * 8;
#pragma unroll
            for (int nt = 0; nt < 4; nt++) {
                uint32_t b0 = fb(kvf[(kl + tq)     * KVS + 8*nt + g]);
                uint32_t b1 = fb(kvf[(kl + tq + 4) * KVS + 8*nt + g]);
                mma8(acc2[nt], a0, a1, a2, a3, b0, b1);
            }
        }
        __syncthreads();
        if (kt < 3) {
#pragma unroll
            for (int i = 0; i < 8; i++) {
                int idx = t + 512 * i, kk = idx >> 3, j = idx & 7;
                *(float4*)&kvf[kk * KVS + j * 4] = st[i];
            }
            __syncthreads();
        }
    }
    // stage per-warp X and reduce across 16 warps
#pragma unroll
    for (int nt = 0; nt < 4; nt++) {
        int d = 8 * nt + 2 * tq;
        *(float2*)&kvf[wid * XWARP +  g      * XSTR + d] = make_float2(acc2[nt].x, acc2[nt].y);
        *(float2*)&kvf[wid * XWARP + (g + 8) * XSTR + d] = make_float2(acc2[nt].z, acc2[nt].w);
    }
    __syncthreads();
    {
        int r = t >> 5, d = t & 31;
        float s = 0.f;
#pragma unroll
        for (int w2 = 0; w2 < 16; w2++) s += kvf[w2 * XWARP + r * XSTR + d];
        g_x[((size_t)b * N_ + q0 + r) * C_ + h * D_ + d] = s;
    }
}

// ---------------------------------------------------------------------------
extern "C" void kernel_launch(void* const* d_in, const int* in_sizes, int n_in,
                              void* d_out, int out_size) {
    (void)in_sizes; (void)n_in; (void)out_size;
    const float* query = (const float*)d_in[0];
    const float* mask  = (const float*)d_in[1];
    const float* Wq    = (const float*)d_in[2];
    const float* bq    = (const float*)d_in[3];
    const float* Wk    = (const float*)d_in[4];
    const float* bk    = (const float*)d_in[5];
    const float* Wv    = (const float*)d_in[6];
    const float* bv    = (const float*)d_in[7];
    const float* Wo    = (const float*)d_in[8];
    const float* bo    = (const float*)d_in[9];

    float* out      = (float*)d_out;
    float* attn_out = out + (size_t)B_ * N_ * C_;

    void* p;
    cudaGetSymbolAddress(&p, g_q);   float* gq = (float*)p;
    cudaGetSymbolAddress(&p, g_k);   float* gk = (float*)p;
    cudaGetSymbolAddress(&p, g_v);   float* gv = (float*)p;
    cudaGetSymbolAddress(&p, g_x);   float* gx = (float*)p;

    cudaFuncSetAttribute(attn_k, cudaFuncAttributeMaxDynamicSharedMemorySize, SM_BYTES);

    dim3 gg(4, 128);
    gemm_qkv<<<gg, 256>>>(query, Wq, bq, gq, Wk, bk, gk, Wv, bv, gv);

    cmax_init<<<(B_ * N_ + 255) / 256, 256>>>();
    cmax_k<<<dim3(8, 8, 4), 256>>>(mask);
    mt_k<<<dim3(N_ / 64, N_ / 64, B_), 256>>>(mask);

    attn_k<<<dim3(N_ / 16, H_, B_), 512, SM_BYTES>>>(attn_out);

    gemm_o<<<gg, 256>>>(gx, Wo, bo, query, out);
}